// round 6
// baseline (speedup 1.0000x reference)
#include <cuda_runtime.h>
#include <cstdint>

#define BB 512
#define TT 512
#define HH 128
#define Z4 512   // 4*H

// ---------------- persistent device scratch (no allocations allowed) ----------------
__device__ float g_w1e[(size_t)BB * TT * HH];   // 134 MB: enc @ W1

// ---------------- transcendentals (identical to the R3-validated math) ----------------
__device__ __forceinline__ float ex2f(float x) {
    float r; asm("ex2.approx.f32 %0, %1;" : "=f"(r) : "f"(x)); return r;
}
__device__ __forceinline__ float rcpf(float x) {
    float r; asm("rcp.approx.f32 %0, %1;" : "=f"(r) : "f"(x)); return r;
}
// tanh(x) = sign(x) * (1 - 2*e/(1+e)), e = exp(-2|x|) via EX2 (abs err ~3e-7)
__device__ __forceinline__ float tanh_acc(float x) {
    float ax = fabsf(x);
    float e  = ex2f(ax * -2.8853900817779268f);
    float r  = rcpf(e + 1.0f);
    float t  = fmaf(-2.0f * e, r, 1.0f);
    return copysignf(t, x);
}
__device__ __forceinline__ float sigm_acc(float x) {
    float e = ex2f(x * -1.4426950408889634f);
    return rcpf(e + 1.0f);
}

// ---------------- w1e[b,t,k] = sum_h enc[b,t,h] * W1[h,k]  (unchanged from R3) ----------------
__global__ void __launch_bounds__(256) k_w1e(const float* __restrict__ enc,
                                             const float* __restrict__ W1) {
    __shared__ float es[32 * HH];
    const int row0 = blockIdx.x * 32;
    const int tid  = threadIdx.x;
    for (int i = tid; i < 32 * HH; i += 256) es[i] = enc[(size_t)row0 * HH + i];
    __syncthreads();
    const int col = tid & 127;
    const int rg  = tid >> 7;
    float acc[16];
#pragma unroll
    for (int i = 0; i < 16; i++) acc[i] = 0.f;
    for (int k = 0; k < HH; k++) {
        float w = __ldg(&W1[k * HH + col]);
#pragma unroll
        for (int i = 0; i < 16; i++)
            acc[i] = fmaf(es[(rg * 16 + i) * HH + k], w, acc[i]);
    }
#pragma unroll
    for (int i = 0; i < 16; i++)
        g_w1e[(size_t)(row0 + rg * 16 + i) * HH + col] = acc[i];
}

// ---------------- persistent per-batch sequence kernel ----------------
// One CTA per batch b (512 CTAs, 256 threads). Runs all 512 steps locally:
//   z = ptr@K + h@R + bias  ->  gates -> h2,c2  ->  wh = h2@W2
//   -> scores_j = V . tanh(w1e[b,j,:] + wh)  -> in-CTA argmax -> ptr feedback
// No cross-CTA communication; all per-step state lives in smem/registers.
__global__ void __launch_bounds__(256, 4) k_seq(
    const float* __restrict__ x,    const float* __restrict__ Kw,
    const float* __restrict__ R,    const float* __restrict__ bias,
    const float* __restrict__ W2,   const float* __restrict__ Vw,
    const float* __restrict__ h0,   const float* __restrict__ c0,
    float* __restrict__ out)
{
    __shared__ __align__(16) float h_s[HH];
    __shared__ __align__(16) float wh_s[HH];
    __shared__ __align__(16) float z_s[Z4];
    __shared__ __align__(16) float sc_s[TT];
    __shared__ unsigned long long red_s;
    __shared__ float ptr_s[2];

    const int b    = blockIdx.x;
    const int tid  = threadIdx.x;
    const int lane = tid & 31;
    const int w    = tid >> 5;

    // initial state
    if (tid < HH) h_s[tid] = h0[b * HH + tid];
    float c_reg = (tid < HH) ? c0[b * HH + tid] : 0.f;
    if (tid == 0) { ptr_s[0] = 1.f; ptr_s[1] = 1.f; red_s = 0ull; }

    // per-thread loop-invariant weights
    const int t0 = 2 * tid;                      // this thread's two z-columns
    const float k0a = __ldg(&Kw[t0]),      k0b = __ldg(&Kw[t0 + 1]);
    const float k1a = __ldg(&Kw[Z4 + t0]), k1b = __ldg(&Kw[Z4 + t0 + 1]);
    const float bta = __ldg(&bias[t0]),    btb = __ldg(&bias[t0 + 1]);
    const float4 vv = __ldg(&((const float4*)Vw)[lane]);
    const float* wb = g_w1e + (size_t)b * TT * HH + lane * 4;

    __syncthreads();

    for (int s = 0; s < TT; s++) {
        // ---- z: each thread computes columns t0, t0+1 (same FMA chain as R3) ----
        const float px = ptr_s[0], py = ptr_s[1];
        float ax = fmaf(py, k1a, px * k0a);
        float ay = fmaf(py, k1b, px * k0b);
#pragma unroll 4
        for (int k = 0; k < HH; k++) {
            const float hk = h_s[k];
            const float2 r = *(const float2*)&R[(size_t)k * Z4 + t0];
            ax = fmaf(hk, r.x, ax);
            ay = fmaf(hk, r.y, ay);
        }
        z_s[t0]     = ax + bta;
        z_s[t0 + 1] = ay + btb;
        __syncthreads();

        // ---- gates (Keras order i,f,g,o); h_s free to overwrite (readers pre-sync) ----
        if (tid < HH) {
            const float zi = z_s[tid];
            const float zf = z_s[HH + tid];
            const float zg = z_s[2 * HH + tid];
            const float zo = z_s[3 * HH + tid];
            const float c2 = fmaf(sigm_acc(zf), c_reg, sigm_acc(zi) * tanh_acc(zg));
            c_reg = c2;
            h_s[tid] = sigm_acc(zo) * tanh_acc(c2);
        }
        __syncthreads();

        // ---- wh = h2 @ W2 (same chain as R3) ----
        if (tid < HH) {
            float a = 0.f;
            for (int k = 0; k < HH; k++)
                a = fmaf(h_s[k], __ldg(&W2[k * HH + tid]), a);
            wh_s[tid] = a;
        }
        __syncthreads();

        // ---- scores + warp-local argmax (identical math/order to R3) ----
        const float4 whv = ((const float4*)wh_s)[lane];
        float bmax = -3.4e38f; int bj = 0;
        for (int j = w; j < TT; j += 8) {
            const float4 e = *(const float4*)(wb + (size_t)j * HH);
            float p = vv.x * tanh_acc(e.x + whv.x);
            p = fmaf(vv.y, tanh_acc(e.y + whv.y), p);
            p = fmaf(vv.z, tanh_acc(e.z + whv.z), p);
            p = fmaf(vv.w, tanh_acc(e.w + whv.w), p);
#pragma unroll
            for (int o = 16; o; o >>= 1) p += __shfl_xor_sync(0xffffffffu, p, o);
            if (lane == 0) {
                sc_s[j] = p;
                if (p > bmax) { bmax = p; bj = j; }   // strict >: first index wins in-warp
            }
        }
        if (lane == 0) {
            unsigned u = __float_as_uint(bmax);
            u = (u & 0x80000000u) ? ~u : (u | 0x80000000u);       // order-preserving map
            atomicMax(&red_s, ((unsigned long long)u << 32) | (unsigned)(~bj)); // min-j ties
        }
        __syncthreads();

        // ---- coalesced output row + ptr feedback for next step ----
        const size_t ofs = ((size_t)b * TT + s) * TT;
        out[ofs + tid]       = sc_s[tid];
        out[ofs + 256 + tid] = sc_s[256 + tid];
        if (tid == 0) {
            const unsigned j = ~(unsigned)(red_s & 0xffffffffu);
            ptr_s[0] = __ldg(&x[((size_t)b * TT + j) * 2 + 0]);
            ptr_s[1] = __ldg(&x[((size_t)b * TT + j) * 2 + 1]);
            red_s = 0ull;
        }
        __syncthreads();
    }
}

// ---------------- launch: 2-node graph ----------------
extern "C" void kernel_launch(void* const* d_in, const int* in_sizes, int n_in,
                              void* d_out, int out_size) {
    (void)in_sizes; (void)n_in; (void)out_size;
    const float* x    = (const float*)d_in[0];   // [512,512,2]
    const float* enc  = (const float*)d_in[1];   // [512,512,128]
    const float* h0   = (const float*)d_in[2];   // [512,128]
    const float* c0   = (const float*)d_in[3];   // [512,128]
    const float* Kw   = (const float*)d_in[4];   // [2,512]
    const float* R    = (const float*)d_in[5];   // [128,512]
    const float* bias = (const float*)d_in[6];   // [512]
    const float* W1   = (const float*)d_in[7];   // [128,128]
    const float* W2   = (const float*)d_in[8];   // [128,128]
    const float* Vw   = (const float*)d_in[9];   // [128,1]
    float* out = (float*)d_out;                  // [512,512,512]

    k_w1e<<<(BB * TT) / 32, 256>>>(enc, W1);
    k_seq<<<BB, 256>>>(x, Kw, R, bias, W2, Vw, h0, c0, out);
}